// round 6
// baseline (speedup 1.0000x reference)
#include <cuda_runtime.h>
#include <math.h>

#define D 128
#define MAX_GRAPHS 4096
#define NSLICE 16
#define SB 64              // setup grid
#define TPB 256
#define WPB 8              // warps per block
#define CH 4               // nodes per warp per iteration
#define S_MAX 136          // max cached nodes per graph (70 KB smem)

// Precomputed small vectors / scratch (no allocation)
__device__ float g_w[D];                         // Wq^T @ Wk
__device__ float g_b0;                           // bq . Wk
__device__ float g_p[D], g_r[D], g_t[D], g_s[D]; // Taylor-collapsed W2 path
__device__ float g_pw[NSLICE][D];                // Wq^T Wk partials
__device__ float g_pu[NSLICE][D];                // W1 @ Wv partials
__device__ int   g_gs[MAX_GRAPHS + 1];           // graph -> first node index
__device__ unsigned g_done = 0;                  // last-block ticket (self-reset)

// ---------------------------------------------------------------------------
// Setup (single kernel, SB blocks):
//  - all blocks: boundary scan of sorted batch into g_gs
//  - blocks 0..15: weight partials (Wq^T Wk, W1 @ Wv); block 0: b0
//  - LAST block to finish: reduce partials, silu Taylor coeffs, fold W2
// ---------------------------------------------------------------------------
__global__ void setup_all(const float* __restrict__ Wq,
                          const float* __restrict__ bq,
                          const float* __restrict__ Wk,
                          const float* __restrict__ Wv,
                          const float* __restrict__ W1,
                          const float* __restrict__ b1,
                          const float* __restrict__ W2,
                          const float* __restrict__ b2,
                          const int* __restrict__ batch,
                          int n_nodes, int n_graphs) {
    __shared__ float wk_s[D], wv_s[D];
    __shared__ float red[D];
    __shared__ float c0[D], c1[D], c2[D], c3[D];
    __shared__ float red2[2][D];
    __shared__ int   is_last;

    int b = blockIdx.x;
    int t = threadIdx.x;

    // ---- boundary scan: g_gs[g] = first i with batch[i] >= g ----
    for (int i = b * blockDim.x + t; i < n_nodes; i += gridDim.x * blockDim.x) {
        int cur = batch[i];
        if (i == 0)
            for (int g = 0; g <= cur; g++) g_gs[g] = 0;
        int nxt = (i + 1 < n_nodes) ? batch[i + 1] : n_graphs;
        for (int g = cur + 1; g <= nxt; g++) g_gs[g] = i + 1;
    }

    int j = t & (D - 1);
    int h = t >> 7;                 // 0/1

    if (b < NSLICE) {
        if (t < D) { wk_s[t] = Wk[t]; wv_s[t] = Wv[t]; }
        __syncthreads();

        // Wq partial: pw[b][j] = sum_{i in [8b,8b+8)} Wq[i][j]*Wk[i]
        {
            float acc = 0.f;
            #pragma unroll
            for (int m = 0; m < 4; m++) {
                int i = b * 8 + h * 4 + m;
                acc += Wq[i * D + j] * wk_s[i];
            }
            if (h == 1) red[j] = acc;
            __syncthreads();
            if (h == 0) g_pw[b][j] = acc + red[j];
            __syncthreads();
        }
        // W1 partial: pu[b][j] = sum_{k in [8b,8b+8)} W1[j][k]*Wv[k]
        {
            int k0 = b * 8 + h * 4;
            float4 w4 = *(const float4*)(W1 + (size_t)j * D + k0);
            float acc = w4.x * wv_s[k0] + w4.y * wv_s[k0 + 1]
                      + w4.z * wv_s[k0 + 2] + w4.w * wv_s[k0 + 3];
            if (h == 1) red[j] = acc;
            __syncthreads();
            if (h == 0) g_pu[b][j] = acc + red[j];
        }
        // b0 (block 0, warp 0)
        if (b == 0 && t < 32) {
            float acc = 0.f;
            for (int i = t; i < D; i += 32) acc += bq[i] * wk_s[i];
            #pragma unroll
            for (int o = 16; o > 0; o >>= 1) acc += __shfl_xor_sync(0xFFFFFFFFu, acc, o);
            if (t == 0) g_b0 = acc;
        }
    }

    // ---- last-block ticket ----
    __threadfence();
    __syncthreads();
    if (t == 0) {
        unsigned a = atomicAdd(&g_done, 1);
        is_last = (a == gridDim.x - 1) ? 1 : 0;
        if (is_last) g_done = 0;             // self-reset for replays
    }
    __syncthreads();
    if (!is_last) return;

    // ---- fold (256 threads): c = t>>7 in {0,1}, j = t&127 ----
    int c = h;
    if (c == 0) {
        float s = 0.f;
        #pragma unroll
        for (int p = 0; p < NSLICE; p++) s += __ldcg(&g_pw[p][j]);
        g_w[j] = s;
    } else {
        float u = 0.f;
        #pragma unroll
        for (int p = 0; p < NSLICE; p++) u += __ldcg(&g_pu[p][j]);

        float x  = b1[j];
        float sg = 1.0f / (1.0f + __expf(-x));
        float sp = sg * (1.0f - sg);
        float f0 = x * sg;
        float f1 = sg + x * sp;
        float f2 = sp * (2.0f + x * (1.0f - 2.0f * sg));
        float om2 = 1.0f - 2.0f * sg;
        float f3 = 3.0f * sp * om2 + x * (sp * om2 * om2 - 2.0f * sp * sp);
        c0[j] = f0;
        c1[j] = u * f1;
        c2[j] = u * u * f2 * 0.5f;
        c3[j] = u * u * u * f3 * (1.0f / 6.0f);
    }
    __syncthreads();

    float ap = 0.f, ar = 0.f, at = 0.f, as = 0.f;
    #pragma unroll
    for (int mm = 0; mm < 16; mm++) {
        int k = c * 64 + mm * 4;
        float4 w4 = *(const float4*)(W2 + (size_t)j * D + k);
        ap += w4.x * c0[k] + w4.y * c0[k+1] + w4.z * c0[k+2] + w4.w * c0[k+3];
        ar += w4.x * c1[k] + w4.y * c1[k+1] + w4.z * c1[k+2] + w4.w * c1[k+3];
        at += w4.x * c2[k] + w4.y * c2[k+1] + w4.z * c2[k+2] + w4.w * c2[k+3];
        as += w4.x * c3[k] + w4.y * c3[k+1] + w4.z * c3[k+2] + w4.w * c3[k+3];
    }
    red2[c][j] = ap; __syncthreads();
    if (c == 0) g_p[j] = b2[j] + red2[0][j] + red2[1][j];
    __syncthreads();
    red2[c][j] = ar; __syncthreads();
    if (c == 0) g_r[j] = red2[0][j] + red2[1][j];
    __syncthreads();
    red2[c][j] = at; __syncthreads();
    if (c == 0) g_t[j] = red2[0][j] + red2[1][j];
    __syncthreads();
    red2[c][j] = as; __syncthreads();
    if (c == 0) g_s[j] = red2[0][j] + red2[1][j];
}

// ---------------------------------------------------------------------------
// Main kernel: ONE BLOCK PER GRAPH. Phase A: load rows ONCE from DRAM,
// cache in dynamic SMEM (+ attn per node), block-local attn sum. Phase B:
// read SMEM, fused epilogue, streaming store. Graphs > S_MAX nodes take a
// block-uniform fallback (reload from L2 + recompute attn).
// ---------------------------------------------------------------------------
__device__ __forceinline__ float silu_f(float x) {
    return x / (1.0f + __expf(-x));
}

__global__ void __launch_bounds__(TPB)
graph_kernel(const float* __restrict__ node,
             const float* __restrict__ spin,
             const float* __restrict__ Wv,
             float* __restrict__ out) {
    extern __shared__ float dyn[];
    float4* s_node = (float4*)dyn;             // S_MAX rows x 32 float4
    float*  s_attn = dyn + (size_t)S_MAX * D;  // S_MAX floats
    __shared__ float s_wsum[WPB];
    __shared__ float s_total;

    int g    = blockIdx.x;
    int tid  = threadIdx.x;
    int wid  = tid >> 5;
    int lane = tid & 31;

    int s = g_gs[g];
    int e = g_gs[g + 1];
    if (e <= s) return;
    bool cached = (e - s) <= S_MAX;

    float4 w4 = ((const float4*)g_w)[lane];
    float  b0 = g_b0;
    float  sp = spin[g];
    float  cc = sp / fmaxf(sp, 1.0f);
    const float SC = 0.08838834764831845f;     // 1/sqrt(128)

    // ---------------- Phase A ----------------
    float wacc = 0.f;
    for (int base = s + wid * CH; base < e; base += WPB * CH) {
        float4 v[CH];
        float  acc[CH];
        #pragma unroll
        for (int r = 0; r < CH; r++) {
            if (base + r < e) {
                v[r] = __ldcs((const float4*)(node + (size_t)(base + r) * D) + lane);
                acc[r] = v[r].x * w4.x + v[r].y * w4.y + v[r].z * w4.z + v[r].w * w4.w;
            } else acc[r] = 0.f;
        }
        #pragma unroll
        for (int o = 16; o > 0; o >>= 1) {
            #pragma unroll
            for (int r = 0; r < CH; r++)
                acc[r] += __shfl_xor_sync(0xFFFFFFFFu, acc[r], o);
        }
        if (cached) {
            #pragma unroll
            for (int r = 0; r < CH; r++)
                if (base + r < e)
                    s_node[(size_t)(base - s + r) * 32 + lane] = v[r];
        }
        if (lane < CH && base + lane < e) {
            float a = acc[0];
            #pragma unroll
            for (int r = 1; r < CH; r++) if (lane == r) a = acc[r];
            float x = cc * (a + b0) * SC;
            float attn = (x > 20.0f) ? x : log1pf(__expf(x));
            wacc += attn;
            if (cached) s_attn[base - s + lane] = attn;
        }
    }
    #pragma unroll
    for (int o = 16; o > 0; o >>= 1) wacc += __shfl_xor_sync(0xFFFFFFFFu, wacc, o);
    if (lane == 0) s_wsum[wid] = wacc;
    __syncthreads();
    if (tid == 0) {
        float tsum = 0.f;
        #pragma unroll
        for (int w = 0; w < WPB; w++) tsum += s_wsum[w];
        s_total = tsum;
    }
    __syncthreads();
    float inv = sp / s_total;                  // alpha_n = attn_n * inv

    // ---------------- Phase B ----------------
    float4 wv = ((const float4*)Wv)[lane];
    float4 p4 = ((const float4*)g_p)[lane];
    float4 r4 = ((const float4*)g_r)[lane];
    float4 t4 = ((const float4*)g_t)[lane];
    float4 s4 = ((const float4*)g_s)[lane];

    if (cached) {
        for (int base = s + wid * CH; base < e; base += WPB * CH) {
            float alpha_l = 0.f;
            if (lane < CH && base + lane < e)
                alpha_l = s_attn[base - s + lane] * inv;
            #pragma unroll
            for (int r = 0; r < CH; r++) {
                int n = base + r;
                if (n >= e) break;
                float4 nv = s_node[(size_t)(n - s) * 32 + lane];
                float alpha = __shfl_sync(0xFFFFFFFFu, alpha_l, r);
                float4 o;
                o.x = nv.x + alpha * wv.x + silu_f(p4.x + alpha * (r4.x + alpha * (t4.x + alpha * s4.x)));
                o.y = nv.y + alpha * wv.y + silu_f(p4.y + alpha * (r4.y + alpha * (t4.y + alpha * s4.y)));
                o.z = nv.z + alpha * wv.z + silu_f(p4.z + alpha * (r4.z + alpha * (t4.z + alpha * s4.z)));
                o.w = nv.w + alpha * wv.w + silu_f(p4.w + alpha * (r4.w + alpha * (t4.w + alpha * s4.w)));
                __stcs((float4*)(out + (size_t)n * D) + lane, o);
            }
        }
    } else {
        // Fallback: reload rows (L2-hot) and recompute attn. Rare.
        for (int base = s + wid * CH; base < e; base += WPB * CH) {
            float4 nv[CH];
            float  acc[CH];
            #pragma unroll
            for (int r = 0; r < CH; r++) {
                if (base + r < e) {
                    nv[r] = __ldcs((const float4*)(node + (size_t)(base + r) * D) + lane);
                    acc[r] = nv[r].x * w4.x + nv[r].y * w4.y + nv[r].z * w4.z + nv[r].w * w4.w;
                } else { nv[r] = make_float4(0.f, 0.f, 0.f, 0.f); acc[r] = 0.f; }
            }
            #pragma unroll
            for (int o = 16; o > 0; o >>= 1) {
                #pragma unroll
                for (int r = 0; r < CH; r++)
                    acc[r] += __shfl_xor_sync(0xFFFFFFFFu, acc[r], o);
            }
            float alpha_l = 0.f;
            if (lane < CH && base + lane < e) {
                float a = acc[0];
                #pragma unroll
                for (int r = 1; r < CH; r++) if (lane == r) a = acc[r];
                float x = cc * (a + b0) * SC;
                float attn = (x > 20.0f) ? x : log1pf(__expf(x));
                alpha_l = attn * inv;
            }
            #pragma unroll
            for (int r = 0; r < CH; r++) {
                int n = base + r;
                if (n >= e) break;
                float alpha = __shfl_sync(0xFFFFFFFFu, alpha_l, r);
                float4 o;
                o.x = nv[r].x + alpha * wv.x + silu_f(p4.x + alpha * (r4.x + alpha * (t4.x + alpha * s4.x)));
                o.y = nv[r].y + alpha * wv.y + silu_f(p4.y + alpha * (r4.y + alpha * (t4.y + alpha * s4.y)));
                o.z = nv[r].z + alpha * wv.z + silu_f(p4.z + alpha * (r4.z + alpha * (t4.z + alpha * s4.z)));
                o.w = nv[r].w + alpha * wv.w + silu_f(p4.w + alpha * (r4.w + alpha * (t4.w + alpha * s4.w)));
                __stcs((float4*)(out + (size_t)n * D) + lane, o);
            }
        }
    }
}

// ---------------------------------------------------------------------------
// Launch. Inputs per metadata order:
// 0 node_scalar [N,128] f32, 1 batch [N] i32, 2 spin [G,1] f32,
// 3 Wq [128,128], 4 bq [128], 5 Wk [128,1], 6 Wv [128,1],
// 7 W1 [128,128], 8 b1 [128], 9 W2 [128,128], 10 b2 [128]
// ---------------------------------------------------------------------------
extern "C" void kernel_launch(void* const* d_in, const int* in_sizes, int n_in,
                              void* d_out, int out_size) {
    const float* node  = (const float*)d_in[0];
    const int*   batch = (const int*)d_in[1];
    const float* spin  = (const float*)d_in[2];
    const float* Wq    = (const float*)d_in[3];
    const float* bq    = (const float*)d_in[4];
    const float* Wk    = (const float*)d_in[5];
    const float* Wv    = (const float*)d_in[6];
    const float* W1    = (const float*)d_in[7];
    const float* b1    = (const float*)d_in[8];
    const float* W2    = (const float*)d_in[9];
    const float* b2    = (const float*)d_in[10];
    float* out = (float*)d_out;

    int n_nodes  = in_sizes[0] / D;
    int n_graphs = in_sizes[2];
    if (n_graphs > MAX_GRAPHS) n_graphs = MAX_GRAPHS;

    setup_all<<<SB, 256>>>(Wq, bq, Wk, Wv, W1, b1, W2, b2, batch, n_nodes, n_graphs);

    size_t smem_bytes = (size_t)S_MAX * D * sizeof(float) + S_MAX * sizeof(float);
    cudaFuncSetAttribute(graph_kernel,
                         cudaFuncAttributeMaxDynamicSharedMemorySize, (int)smem_bytes);
    graph_kernel<<<n_graphs, TPB, smem_bytes>>>(node, spin, Wv, out);
}

// round 7
// speedup vs baseline: 1.0329x; 1.0329x over previous
#include <cuda_runtime.h>
#include <math.h>

#define D 128
#define MAX_GRAPHS 4096
#define NSLICE 16
#define TPB 512
#define WPB 16             // warps per block
#define CH 4               // nodes per warp per iteration
#define REG_IT 2           // register-cached iterations (covers WPB*CH*REG_IT nodes)
#define REG_NODES (WPB*CH*REG_IT)   // 128
#define S_ATT 512          // smem attn cache capacity (nodes per graph)

// Precomputed small vectors / scratch (no allocation)
__device__ float g_w[D];                         // Wq^T @ Wk
__device__ float g_b0;                           // bq . Wk
__device__ float g_A[D], g_Bp[D], g_C[D], g_E[D];// fully-collapsed epilogue poly
__device__ float g_pw[NSLICE][D];                // Wq^T Wk partials
__device__ float g_pu[NSLICE][D];                // W1 @ Wv partials
__device__ int   g_gs[MAX_GRAPHS + 1];           // graph -> first node index

// ---------------------------------------------------------------------------
// Setup K1: boundary scan (vectorized) + weight partials + b0.
// ---------------------------------------------------------------------------
__global__ void setup1(const float* __restrict__ Wq,
                       const float* __restrict__ bq,
                       const float* __restrict__ Wk,
                       const float* __restrict__ Wv,
                       const float* __restrict__ W1,
                       const int* __restrict__ batch,
                       int n_nodes, int n_graphs) {
    __shared__ float wk_s[D], wv_s[D];
    __shared__ float red[D];

    int b = blockIdx.x;
    int t = threadIdx.x;

    // ---- boundary scan, 4 nodes per thread, int4 loads ----
    int n4 = (n_nodes + 3) >> 2;
    for (int i4 = b * blockDim.x + t; i4 < n4; i4 += gridDim.x * blockDim.x) {
        int i = i4 * 4;
        int rem = n_nodes - i;
        int m = rem < 4 ? rem : 4;
        int c0, c1 = 0, c2 = 0, c3 = 0;
        if (rem >= 4) {
            int4 bb = *(const int4*)(batch + i);
            c0 = bb.x; c1 = bb.y; c2 = bb.z; c3 = bb.w;
        } else {
            c0 = batch[i];
            if (rem > 1) c1 = batch[i + 1];
            if (rem > 2) c2 = batch[i + 2];
        }
        int c4 = (i + 4 < n_nodes) ? batch[i + 4] : n_graphs;
        int cs[5] = {c0, c1, c2, c3, c4};
        if (i == 0)
            for (int g = 0; g <= c0; g++) g_gs[g] = 0;
        #pragma unroll
        for (int k = 0; k < 4; k++) {
            if (k >= m) break;
            int cur = cs[k];
            int nxt = (k < m - 1) ? cs[k + 1]
                                  : ((i + m < n_nodes) ? c4 : n_graphs);
            for (int g = cur + 1; g <= nxt; g++) g_gs[g] = i + k + 1;
        }
    }

    if (b >= NSLICE) return;

    int j = t & (D - 1);
    int h = (t >> 7) & 1;          // use threads 0..255 pattern; blocks have 256

    if (t < D) { wk_s[t] = Wk[t]; wv_s[t] = Wv[t]; }
    __syncthreads();

    // Wq partial: pw[b][j] = sum_{i in [8b,8b+8)} Wq[i][j]*Wk[i]
    {
        float acc = 0.f;
        #pragma unroll
        for (int m = 0; m < 4; m++) {
            int i = b * 8 + h * 4 + m;
            acc += Wq[i * D + j] * wk_s[i];
        }
        if (h == 1) red[j] = acc;
        __syncthreads();
        if (h == 0) g_pw[b][j] = acc + red[j];
        __syncthreads();
    }
    // W1 partial: pu[b][j] = sum_{k in [8b,8b+8)} W1[j][k]*Wv[k]
    {
        int k0 = b * 8 + h * 4;
        float4 w4 = *(const float4*)(W1 + (size_t)j * D + k0);
        float acc = w4.x * wv_s[k0] + w4.y * wv_s[k0 + 1]
                  + w4.z * wv_s[k0 + 2] + w4.w * wv_s[k0 + 3];
        if (h == 1) red[j] = acc;
        __syncthreads();
        if (h == 0) g_pu[b][j] = acc + red[j];
    }
    // b0 (block 0, warp 0)
    if (b == 0 && t < 32) {
        float acc = 0.f;
        for (int i = t; i < D; i += 32) acc += bq[i] * wk_s[i];
        #pragma unroll
        for (int o = 16; o > 0; o >>= 1) acc += __shfl_xor_sync(0xFFFFFFFFu, acc, o);
        if (t == 0) g_b0 = acc;
    }
}

// ---------------------------------------------------------------------------
// Setup K2: reduce partials, inner silu Taylor (at b1), fold through W2 to
// get p,r,t,s; then OUTER silu Taylor (at p) collapses the epilogue to a pure
// cubic: out = node + A + alpha*B' + alpha^2*C + alpha^3*E, B' includes Wv.
// ---------------------------------------------------------------------------
__global__ void setup_fold(const float* __restrict__ b1,
                           const float* __restrict__ W2,
                           const float* __restrict__ b2,
                           const float* __restrict__ Wv) {
    __shared__ float c0[D], c1[D], c2[D], c3[D];
    __shared__ float red[8][D];

    int t = threadIdx.x;
    int c = t >> 7;          // 0..7
    int j = t & (D - 1);

    if (c == 0) {
        float s = 0.f;
        #pragma unroll
        for (int p = 0; p < NSLICE; p++) s += g_pw[p][j];
        g_w[j] = s;
    } else if (c == 1) {
        float u = 0.f;
        #pragma unroll
        for (int p = 0; p < NSLICE; p++) u += g_pu[p][j];

        float x  = b1[j];
        float sg = 1.0f / (1.0f + __expf(-x));
        float spd = sg * (1.0f - sg);
        float f0 = x * sg;
        float f1 = sg + x * spd;
        float f2 = spd * (2.0f + x * (1.0f - 2.0f * sg));
        float om2 = 1.0f - 2.0f * sg;
        float f3 = 3.0f * spd * om2 + x * (spd * om2 * om2 - 2.0f * spd * spd);
        c0[j] = f0;
        c1[j] = u * f1;
        c2[j] = u * u * f2 * 0.5f;
        c3[j] = u * u * u * f3 * (1.0f / 6.0f);
    }
    __syncthreads();

    float ap = 0.f, ar = 0.f, at = 0.f, as = 0.f;
    #pragma unroll
    for (int mm = 0; mm < 4; mm++) {
        int k = c * 16 + mm * 4;
        float4 w4 = *(const float4*)(W2 + (size_t)j * D + k);
        ap += w4.x * c0[k] + w4.y * c0[k+1] + w4.z * c0[k+2] + w4.w * c0[k+3];
        ar += w4.x * c1[k] + w4.y * c1[k+1] + w4.z * c1[k+2] + w4.w * c1[k+3];
        at += w4.x * c2[k] + w4.y * c2[k+1] + w4.z * c2[k+2] + w4.w * c2[k+3];
        as += w4.x * c3[k] + w4.y * c3[k+1] + w4.z * c3[k+2] + w4.w * c3[k+3];
    }
    float p_v = 0.f, r_v = 0.f, t_v = 0.f, s_v = 0.f;
    red[c][j] = ap; __syncthreads();
    if (c == 0) { p_v = b2[j];
        #pragma unroll
        for (int p = 0; p < 8; p++) p_v += red[p][j]; }
    __syncthreads();
    red[c][j] = ar; __syncthreads();
    if (c == 0) {
        #pragma unroll
        for (int p = 0; p < 8; p++) r_v += red[p][j]; }
    __syncthreads();
    red[c][j] = at; __syncthreads();
    if (c == 0) {
        #pragma unroll
        for (int p = 0; p < 8; p++) t_v += red[p][j]; }
    __syncthreads();
    red[c][j] = as; __syncthreads();
    if (c == 0) {
        #pragma unroll
        for (int p = 0; p < 8; p++) s_v += red[p][j];

        // outer silu Taylor at x = p_v
        float x  = p_v;
        float sg = 1.0f / (1.0f + __expf(-x));
        float spd = sg * (1.0f - sg);
        float d0 = x * sg;                              // silu(p)
        float d1 = sg + x * spd;                        // silu'
        float d2 = spd * (2.0f + x * (1.0f - 2.0f * sg)); // silu''
        float om2 = 1.0f - 2.0f * sg;
        float d3 = 3.0f * spd * om2 + x * (spd * om2 * om2 - 2.0f * spd * spd);

        g_A[j]  = d0;
        g_Bp[j] = Wv[j] + d1 * r_v;
        g_C[j]  = 0.5f * d2 * r_v * r_v + d1 * t_v;
        g_E[j]  = (1.0f / 6.0f) * d3 * r_v * r_v * r_v + d2 * r_v * t_v + d1 * s_v;
    }
}

// ---------------------------------------------------------------------------
// Main kernel: ONE BLOCK PER GRAPH, rows cached in REGISTERS across phases.
// Phase A: load rows once, 6-shfl multi-reduce -> attn (smem) + block sum.
// Phase B: pure-FMA cubic epilogue from registers, streaming store.
// Overflow nodes (>REG_NODES) reload from L2; attn recomputed past S_ATT.
// ---------------------------------------------------------------------------
__global__ void __launch_bounds__(TPB)
graph_kernel(const float* __restrict__ node,
             const float* __restrict__ spin,
             float* __restrict__ out) {
    __shared__ float s_attn[S_ATT];
    __shared__ float s_wsum[WPB];
    __shared__ float s_total;

    int g    = blockIdx.x;
    int tid  = threadIdx.x;
    int wid  = tid >> 5;
    int lane = tid & 31;

    int s = g_gs[g];
    int e = g_gs[g + 1];
    if (e <= s) return;

    float4 w4 = ((const float4*)g_w)[lane];
    float  b0 = g_b0;
    float  sp = spin[g];
    float  cc = sp / fmaxf(sp, 1.0f);
    const float SC = 0.08838834764831845f;   // 1/sqrt(128)
    bool bA = lane & 1, bB = lane & 2;

    float4 v[REG_IT][CH];
    float  wacc = 0.f;

    // ---------------- Phase A (register-cached range) ----------------
    #pragma unroll
    for (int it = 0; it < REG_IT; it++) {
        int base = s + (it * WPB + wid) * CH;
        if (base < e) {
            #pragma unroll
            for (int r = 0; r < CH; r++)
                v[it][r] = (base + r < e)
                    ? __ldcs((const float4*)(node + (size_t)(base + r) * D) + lane)
                    : make_float4(0.f, 0.f, 0.f, 0.f);
            float a0 = v[it][0].x*w4.x + v[it][0].y*w4.y + v[it][0].z*w4.z + v[it][0].w*w4.w;
            float a1 = v[it][1].x*w4.x + v[it][1].y*w4.y + v[it][1].z*w4.z + v[it][1].w*w4.w;
            float a2 = v[it][2].x*w4.x + v[it][2].y*w4.y + v[it][2].z*w4.z + v[it][2].w*w4.w;
            float a3 = v[it][3].x*w4.x + v[it][3].y*w4.y + v[it][3].z*w4.z + v[it][3].w*w4.w;
            // 6-shfl multi-value reduce: lane l ends with node (l&3)'s full dot
            float x01 = bA ? a1 : a0, y01 = bA ? a0 : a1;
            x01 += __shfl_xor_sync(0xFFFFFFFFu, y01, 1);
            float x23 = bA ? a3 : a2, y23 = bA ? a2 : a3;
            x23 += __shfl_xor_sync(0xFFFFFFFFu, y23, 1);
            float xa = bB ? x23 : x01, ya = bB ? x01 : x23;
            xa += __shfl_xor_sync(0xFFFFFFFFu, ya, 2);
            xa += __shfl_xor_sync(0xFFFFFFFFu, xa, 4);
            xa += __shfl_xor_sync(0xFFFFFFFFu, xa, 8);
            xa += __shfl_xor_sync(0xFFFFFFFFu, xa, 16);
            if (lane < CH && base + lane < e) {
                float x = cc * (xa + b0) * SC;
                float attn = (x > 20.0f) ? x : log1pf(__expf(x));
                s_attn[base + lane - s] = attn;
                wacc += attn;
            }
        }
    }
    // Overflow nodes (rare): no register cache
    for (int base = s + REG_NODES + wid * CH; base < e; base += WPB * CH) {
        float4 vv[CH];
        #pragma unroll
        for (int r = 0; r < CH; r++)
            vv[r] = (base + r < e)
                ? ((const float4*)(node + (size_t)(base + r) * D))[lane]
                : make_float4(0.f, 0.f, 0.f, 0.f);
        float a0 = vv[0].x*w4.x + vv[0].y*w4.y + vv[0].z*w4.z + vv[0].w*w4.w;
        float a1 = vv[1].x*w4.x + vv[1].y*w4.y + vv[1].z*w4.z + vv[1].w*w4.w;
        float a2 = vv[2].x*w4.x + vv[2].y*w4.y + vv[2].z*w4.z + vv[2].w*w4.w;
        float a3 = vv[3].x*w4.x + vv[3].y*w4.y + vv[3].z*w4.z + vv[3].w*w4.w;
        float x01 = bA ? a1 : a0, y01 = bA ? a0 : a1;
        x01 += __shfl_xor_sync(0xFFFFFFFFu, y01, 1);
        float x23 = bA ? a3 : a2, y23 = bA ? a2 : a3;
        x23 += __shfl_xor_sync(0xFFFFFFFFu, y23, 1);
        float xa = bB ? x23 : x01, ya = bB ? x01 : x23;
        xa += __shfl_xor_sync(0xFFFFFFFFu, ya, 2);
        xa += __shfl_xor_sync(0xFFFFFFFFu, xa, 4);
        xa += __shfl_xor_sync(0xFFFFFFFFu, xa, 8);
        xa += __shfl_xor_sync(0xFFFFFFFFu, xa, 16);
        if (lane < CH && base + lane < e) {
            float x = cc * (xa + b0) * SC;
            float attn = (x > 20.0f) ? x : log1pf(__expf(x));
            int idx = base + lane - s;
            if (idx < S_ATT) s_attn[idx] = attn;
            wacc += attn;
        }
    }

    #pragma unroll
    for (int o = 16; o > 0; o >>= 1) wacc += __shfl_xor_sync(0xFFFFFFFFu, wacc, o);
    if (lane == 0) s_wsum[wid] = wacc;
    __syncthreads();
    if (tid == 0) {
        float ts = 0.f;
        #pragma unroll
        for (int w = 0; w < WPB; w++) ts += s_wsum[w];
        s_total = ts;
    }
    __syncthreads();
    float inv = sp / s_total;

    // ---------------- Phase B: pure-FMA cubic epilogue ----------------
    float4 A4 = ((const float4*)g_A)[lane];
    float4 B4 = ((const float4*)g_Bp)[lane];
    float4 C4 = ((const float4*)g_C)[lane];
    float4 E4 = ((const float4*)g_E)[lane];

    #pragma unroll
    for (int it = 0; it < REG_IT; it++) {
        int base = s + (it * WPB + wid) * CH;
        if (base < e) {
            float alpha_l = 0.f;
            if (lane < CH && base + lane < e)
                alpha_l = s_attn[base + lane - s] * inv;
            #pragma unroll
            for (int r = 0; r < CH; r++) {
                int n = base + r;
                if (n < e) {
                    float al = __shfl_sync(0xFFFFFFFFu, alpha_l, r);
                    float4 nv = v[it][r];
                    float4 o;
                    o.x = fmaf(al, fmaf(al, fmaf(al, E4.x, C4.x), B4.x), nv.x + A4.x);
                    o.y = fmaf(al, fmaf(al, fmaf(al, E4.y, C4.y), B4.y), nv.y + A4.y);
                    o.z = fmaf(al, fmaf(al, fmaf(al, E4.z, C4.z), B4.z), nv.z + A4.z);
                    o.w = fmaf(al, fmaf(al, fmaf(al, E4.w, C4.w), B4.w), nv.w + A4.w);
                    __stcs((float4*)(out + (size_t)n * D) + lane, o);
                }
            }
        }
    }
    // Overflow: reload (L2-hot); attn from smem or recompute past S_ATT
    for (int base = s + REG_NODES + wid * CH; base < e; base += WPB * CH) {
        float4 nv[CH];
        #pragma unroll
        for (int r = 0; r < CH; r++)
            nv[r] = (base + r < e)
                ? ((const float4*)(node + (size_t)(base + r) * D))[lane]
                : make_float4(0.f, 0.f, 0.f, 0.f);
        float alpha_l = 0.f;
        if (base - s < S_ATT) {                 // chunk fully below boundary (CH-aligned)
            if (lane < CH && base + lane < e)
                alpha_l = s_attn[base + lane - s] * inv;
        } else {
            float a0 = nv[0].x*w4.x + nv[0].y*w4.y + nv[0].z*w4.z + nv[0].w*w4.w;
            float a1 = nv[1].x*w4.x + nv[1].y*w4.y + nv[1].z*w4.z + nv[1].w*w4.w;
            float a2 = nv[2].x*w4.x + nv[2].y*w4.y + nv[2].z*w4.z + nv[2].w*w4.w;
            float a3 = nv[3].x*w4.x + nv[3].y*w4.y + nv[3].z*w4.z + nv[3].w*w4.w;
            float x01 = bA ? a1 : a0, y01 = bA ? a0 : a1;
            x01 += __shfl_xor_sync(0xFFFFFFFFu, y01, 1);
            float x23 = bA ? a3 : a2, y23 = bA ? a2 : a3;
            x23 += __shfl_xor_sync(0xFFFFFFFFu, y23, 1);
            float xa = bB ? x23 : x01, ya = bB ? x01 : x23;
            xa += __shfl_xor_sync(0xFFFFFFFFu, ya, 2);
            xa += __shfl_xor_sync(0xFFFFFFFFu, xa, 4);
            xa += __shfl_xor_sync(0xFFFFFFFFu, xa, 8);
            xa += __shfl_xor_sync(0xFFFFFFFFu, xa, 16);
            if (lane < CH && base + lane < e) {
                float x = cc * (xa + b0) * SC;
                float attn = (x > 20.0f) ? x : log1pf(__expf(x));
                alpha_l = attn * inv;
            }
        }
        #pragma unroll
        for (int r = 0; r < CH; r++) {
            int n = base + r;
            if (n < e) {
                float al = __shfl_sync(0xFFFFFFFFu, alpha_l, r);
                float4 o;
                o.x = fmaf(al, fmaf(al, fmaf(al, E4.x, C4.x), B4.x), nv[r].x + A4.x);
                o.y = fmaf(al, fmaf(al, fmaf(al, E4.y, C4.y), B4.y), nv[r].y + A4.y);
                o.z = fmaf(al, fmaf(al, fmaf(al, E4.z, C4.z), B4.z), nv[r].z + A4.z);
                o.w = fmaf(al, fmaf(al, fmaf(al, E4.w, C4.w), B4.w), nv[r].w + A4.w);
                __stcs((float4*)(out + (size_t)n * D) + lane, o);
            }
        }
    }
}

// ---------------------------------------------------------------------------
// Launch. Inputs per metadata order:
// 0 node_scalar [N,128] f32, 1 batch [N] i32, 2 spin [G,1] f32,
// 3 Wq [128,128], 4 bq [128], 5 Wk [128,1], 6 Wv [128,1],
// 7 W1 [128,128], 8 b1 [128], 9 W2 [128,128], 10 b2 [128]
// ---------------------------------------------------------------------------
extern "C" void kernel_launch(void* const* d_in, const int* in_sizes, int n_in,
                              void* d_out, int out_size) {
    const float* node  = (const float*)d_in[0];
    const int*   batch = (const int*)d_in[1];
    const float* spin  = (const float*)d_in[2];
    const float* Wq    = (const float*)d_in[3];
    const float* bq    = (const float*)d_in[4];
    const float* Wk    = (const float*)d_in[5];
    const float* Wv    = (const float*)d_in[6];
    const float* W1    = (const float*)d_in[7];
    const float* b1    = (const float*)d_in[8];
    const float* W2    = (const float*)d_in[9];
    const float* b2    = (const float*)d_in[10];
    float* out = (float*)d_out;

    int n_nodes  = in_sizes[0] / D;
    int n_graphs = in_sizes[2];
    if (n_graphs > MAX_GRAPHS) n_graphs = MAX_GRAPHS;

    int n4 = (n_nodes + 3) / 4;
    int sblocks = (n4 + 255) / 256;
    if (sblocks < NSLICE) sblocks = NSLICE;
    setup1<<<sblocks, 256>>>(Wq, bq, Wk, Wv, W1, batch, n_nodes, n_graphs);
    setup_fold<<<1, 1024>>>(b1, W2, b2, Wv);
    graph_kernel<<<n_graphs, TPB>>>(node, spin, out);
}

// round 8
// speedup vs baseline: 1.3320x; 1.2896x over previous
#include <cuda_runtime.h>
#include <math.h>

#define D 128
#define MAX_GRAPHS 4096
#define NSLICE 16
#define TPB 256
#define WPB 8              // warps per block
#define CH 4               // nodes per warp per iteration
#define S_ATT 1024         // smem attn cache (nodes per graph); fallback beyond

// Precomputed small vectors / scratch (no allocation)
__device__ float g_w[D];                          // Wq^T @ Wk
__device__ float g_b0;                            // bq . Wk
__device__ float g_A[D], g_Bp[D], g_C[D], g_E[D]; // fully-collapsed epilogue poly
__device__ float g_pw[NSLICE][D];                 // Wq^T Wk partials
__device__ float g_pu[NSLICE][D];                 // W1 @ Wv partials
__device__ int   g_gs[MAX_GRAPHS + 1];            // graph -> first node index

// ---------------------------------------------------------------------------
// Setup K1: boundary scan + weight partials + b0.
// ---------------------------------------------------------------------------
__global__ void setup1(const float* __restrict__ Wq,
                       const float* __restrict__ bq,
                       const float* __restrict__ Wk,
                       const float* __restrict__ Wv,
                       const float* __restrict__ W1,
                       const int* __restrict__ batch,
                       int n_nodes, int n_graphs) {
    __shared__ float wk_s[D], wv_s[D];
    __shared__ float red[D];

    int b = blockIdx.x;
    int t = threadIdx.x;

    // ---- boundary scan: g_gs[g] = first i with batch[i] >= g ----
    for (int i = b * blockDim.x + t; i < n_nodes; i += gridDim.x * blockDim.x) {
        int cur = batch[i];
        if (i == 0)
            for (int g = 0; g <= cur; g++) g_gs[g] = 0;
        int nxt = (i + 1 < n_nodes) ? batch[i + 1] : n_graphs;
        for (int g = cur + 1; g <= nxt; g++) g_gs[g] = i + 1;
    }

    if (b >= NSLICE) return;

    int j = t & (D - 1);
    int h = t >> 7;                // 0/1

    if (t < D) { wk_s[t] = Wk[t]; wv_s[t] = Wv[t]; }
    __syncthreads();

    // Wq partial: pw[b][j] = sum_{i in [8b,8b+8)} Wq[i][j]*Wk[i]
    {
        float acc = 0.f;
        #pragma unroll
        for (int m = 0; m < 4; m++) {
            int i = b * 8 + h * 4 + m;
            acc += Wq[i * D + j] * wk_s[i];
        }
        if (h == 1) red[j] = acc;
        __syncthreads();
        if (h == 0) g_pw[b][j] = acc + red[j];
        __syncthreads();
    }
    // W1 partial: pu[b][j] = sum_{k in [8b,8b+8)} W1[j][k]*Wv[k]
    {
        int k0 = b * 8 + h * 4;
        float4 w4 = *(const float4*)(W1 + (size_t)j * D + k0);
        float acc = w4.x * wv_s[k0] + w4.y * wv_s[k0 + 1]
                  + w4.z * wv_s[k0 + 2] + w4.w * wv_s[k0 + 3];
        if (h == 1) red[j] = acc;
        __syncthreads();
        if (h == 0) g_pu[b][j] = acc + red[j];
    }
    // b0 (block 0, warp 0)
    if (b == 0 && t < 32) {
        float acc = 0.f;
        for (int i = t; i < D; i += 32) acc += bq[i] * wk_s[i];
        #pragma unroll
        for (int o = 16; o > 0; o >>= 1) acc += __shfl_xor_sync(0xFFFFFFFFu, acc, o);
        if (t == 0) g_b0 = acc;
    }
}

// ---------------------------------------------------------------------------
// Setup K2: reduce partials, inner silu Taylor (at b1), fold through W2 to
// p,r,t,s; outer silu Taylor (at p) collapses the epilogue to a pure cubic:
// out = node + A + alpha*B' + alpha^2*C + alpha^3*E   (B' includes Wv).
// ---------------------------------------------------------------------------
__global__ void setup_fold(const float* __restrict__ b1,
                           const float* __restrict__ W2,
                           const float* __restrict__ b2,
                           const float* __restrict__ Wv) {
    __shared__ float c0[D], c1[D], c2[D], c3[D];
    __shared__ float red[8][D];

    int t = threadIdx.x;
    int c = t >> 7;          // 0..7
    int j = t & (D - 1);

    if (c == 0) {
        float s = 0.f;
        #pragma unroll
        for (int p = 0; p < NSLICE; p++) s += g_pw[p][j];
        g_w[j] = s;
    } else if (c == 1) {
        float u = 0.f;
        #pragma unroll
        for (int p = 0; p < NSLICE; p++) u += g_pu[p][j];

        float x  = b1[j];
        float sg = 1.0f / (1.0f + __expf(-x));
        float spd = sg * (1.0f - sg);
        float f0 = x * sg;
        float f1 = sg + x * spd;
        float f2 = spd * (2.0f + x * (1.0f - 2.0f * sg));
        float om2 = 1.0f - 2.0f * sg;
        float f3 = 3.0f * spd * om2 + x * (spd * om2 * om2 - 2.0f * spd * spd);
        c0[j] = f0;
        c1[j] = u * f1;
        c2[j] = u * u * f2 * 0.5f;
        c3[j] = u * u * u * f3 * (1.0f / 6.0f);
    }
    __syncthreads();

    float ap = 0.f, ar = 0.f, at = 0.f, as = 0.f;
    #pragma unroll
    for (int mm = 0; mm < 4; mm++) {
        int k = c * 16 + mm * 4;
        float4 w4 = *(const float4*)(W2 + (size_t)j * D + k);
        ap += w4.x * c0[k] + w4.y * c0[k+1] + w4.z * c0[k+2] + w4.w * c0[k+3];
        ar += w4.x * c1[k] + w4.y * c1[k+1] + w4.z * c1[k+2] + w4.w * c1[k+3];
        at += w4.x * c2[k] + w4.y * c2[k+1] + w4.z * c2[k+2] + w4.w * c2[k+3];
        as += w4.x * c3[k] + w4.y * c3[k+1] + w4.z * c3[k+2] + w4.w * c3[k+3];
    }
    float p_v = 0.f, r_v = 0.f, t_v = 0.f, s_v = 0.f;
    red[c][j] = ap; __syncthreads();
    if (c == 0) { p_v = b2[j];
        #pragma unroll
        for (int p = 0; p < 8; p++) p_v += red[p][j]; }
    __syncthreads();
    red[c][j] = ar; __syncthreads();
    if (c == 0) {
        #pragma unroll
        for (int p = 0; p < 8; p++) r_v += red[p][j]; }
    __syncthreads();
    red[c][j] = at; __syncthreads();
    if (c == 0) {
        #pragma unroll
        for (int p = 0; p < 8; p++) t_v += red[p][j]; }
    __syncthreads();
    red[c][j] = as; __syncthreads();
    if (c == 0) {
        #pragma unroll
        for (int p = 0; p < 8; p++) s_v += red[p][j];

        // outer silu Taylor at x = p_v
        float x  = p_v;
        float sg = 1.0f / (1.0f + __expf(-x));
        float spd = sg * (1.0f - sg);
        float d0 = x * sg;
        float d1 = sg + x * spd;
        float d2 = spd * (2.0f + x * (1.0f - 2.0f * sg));
        float om2 = 1.0f - 2.0f * sg;
        float d3 = 3.0f * spd * om2 + x * (spd * om2 * om2 - 2.0f * spd * spd);

        g_A[j]  = d0;
        g_Bp[j] = Wv[j] + d1 * r_v;
        g_C[j]  = 0.5f * d2 * r_v * r_v + d1 * t_v;
        g_E[j]  = (1.0f / 6.0f) * d3 * r_v * r_v * r_v + d2 * r_v * t_v + d1 * s_v;
    }
}

// ---------------------------------------------------------------------------
// Main kernel: ONE BLOCK PER GRAPH (R5 skeleton). Phase A: dot -> softplus,
// attn cached in 4KB smem, block-local sum (no atomics). Phase B: reload
// rows (L2-hot), pure-FMA cubic epilogue, streaming store.
// ---------------------------------------------------------------------------
__global__ void __launch_bounds__(TPB)
graph_kernel(const float* __restrict__ node,
             const float* __restrict__ spin,
             float* __restrict__ out) {
    __shared__ float s_attn[S_ATT];
    __shared__ float s_wsum[WPB];
    __shared__ float s_total;

    int g    = blockIdx.x;
    int tid  = threadIdx.x;
    int wid  = tid >> 5;
    int lane = tid & 31;

    int s = g_gs[g];
    int e = g_gs[g + 1];
    if (e <= s) return;

    float4 w4 = ((const float4*)g_w)[lane];
    float  b0 = g_b0;
    float  sp = spin[g];
    float  cc = sp / fmaxf(sp, 1.0f);
    const float SC = 0.08838834764831845f;   // 1/sqrt(128)
    bool bA = lane & 1, bB = lane & 2;

    // ---------------- Phase A ----------------
    float wacc = 0.f;
    for (int base = s + wid * CH; base < e; base += WPB * CH) {
        float4 v[CH];
        #pragma unroll
        for (int r = 0; r < CH; r++)
            v[r] = (base + r < e)
                ? __ldcg((const float4*)(node + (size_t)(base + r) * D) + lane)
                : make_float4(0.f, 0.f, 0.f, 0.f);
        float a0 = v[0].x*w4.x + v[0].y*w4.y + v[0].z*w4.z + v[0].w*w4.w;
        float a1 = v[1].x*w4.x + v[1].y*w4.y + v[1].z*w4.z + v[1].w*w4.w;
        float a2 = v[2].x*w4.x + v[2].y*w4.y + v[2].z*w4.z + v[2].w*w4.w;
        float a3 = v[3].x*w4.x + v[3].y*w4.y + v[3].z*w4.z + v[3].w*w4.w;
        // 6-shfl merge reduce: lane l ends with node (l&3)'s full dot
        float x01 = bA ? a1 : a0, y01 = bA ? a0 : a1;
        x01 += __shfl_xor_sync(0xFFFFFFFFu, y01, 1);
        float x23 = bA ? a3 : a2, y23 = bA ? a2 : a3;
        x23 += __shfl_xor_sync(0xFFFFFFFFu, y23, 1);
        float xa = bB ? x23 : x01, ya = bB ? x01 : x23;
        xa += __shfl_xor_sync(0xFFFFFFFFu, ya, 2);
        xa += __shfl_xor_sync(0xFFFFFFFFu, xa, 4);
        xa += __shfl_xor_sync(0xFFFFFFFFu, xa, 8);
        xa += __shfl_xor_sync(0xFFFFFFFFu, xa, 16);
        if (lane < CH && base + lane < e) {
            float x = cc * (xa + b0) * SC;
            float attn = (x > 20.0f) ? x : log1pf(__expf(x));
            wacc += attn;
            int idx = base + lane - s;
            if (idx < S_ATT) s_attn[idx] = attn;
        }
    }
    #pragma unroll
    for (int o = 16; o > 0; o >>= 1) wacc += __shfl_xor_sync(0xFFFFFFFFu, wacc, o);
    if (lane == 0) s_wsum[wid] = wacc;
    __syncthreads();
    if (tid == 0) {
        float ts = 0.f;
        #pragma unroll
        for (int w = 0; w < WPB; w++) ts += s_wsum[w];
        s_total = ts;
    }
    __syncthreads();
    float inv = sp / s_total;

    // ---------------- Phase B: pure-FMA cubic epilogue ----------------
    float4 A4 = ((const float4*)g_A)[lane];
    float4 B4 = ((const float4*)g_Bp)[lane];
    float4 C4 = ((const float4*)g_C)[lane];
    float4 E4 = ((const float4*)g_E)[lane];

    for (int base = s + wid * CH; base < e; base += WPB * CH) {
        float4 nv[CH];
        #pragma unroll
        for (int r = 0; r < CH; r++)
            nv[r] = (base + r < e)
                ? ((const float4*)(node + (size_t)(base + r) * D))[lane]
                : make_float4(0.f, 0.f, 0.f, 0.f);

        if (base - s + CH <= S_ATT) {
            // fast path: alpha via smem broadcast, no reduce, no silu
            #pragma unroll
            for (int r = 0; r < CH; r++) {
                int n = base + r;
                if (n >= e) break;
                float al = s_attn[n - s] * inv;     // LDS broadcast
                float4 o;
                o.x = fmaf(al, fmaf(al, fmaf(al, E4.x, C4.x), B4.x), nv[r].x + A4.x);
                o.y = fmaf(al, fmaf(al, fmaf(al, E4.y, C4.y), B4.y), nv[r].y + A4.y);
                o.z = fmaf(al, fmaf(al, fmaf(al, E4.z, C4.z), B4.z), nv[r].z + A4.z);
                o.w = fmaf(al, fmaf(al, fmaf(al, E4.w, C4.w), B4.w), nv[r].w + A4.w);
                __stcs((float4*)(out + (size_t)n * D) + lane, o);
            }
        } else {
            // fallback (graphs > S_ATT nodes): recompute attn from reloaded rows
            float a0 = nv[0].x*w4.x + nv[0].y*w4.y + nv[0].z*w4.z + nv[0].w*w4.w;
            float a1 = nv[1].x*w4.x + nv[1].y*w4.y + nv[1].z*w4.z + nv[1].w*w4.w;
            float a2 = nv[2].x*w4.x + nv[2].y*w4.y + nv[2].z*w4.z + nv[2].w*w4.w;
            float a3 = nv[3].x*w4.x + nv[3].y*w4.y + nv[3].z*w4.z + nv[3].w*w4.w;
            float x01 = bA ? a1 : a0, y01 = bA ? a0 : a1;
            x01 += __shfl_xor_sync(0xFFFFFFFFu, y01, 1);
            float x23 = bA ? a3 : a2, y23 = bA ? a2 : a3;
            x23 += __shfl_xor_sync(0xFFFFFFFFu, y23, 1);
            float xa = bB ? x23 : x01, ya = bB ? x01 : x23;
            xa += __shfl_xor_sync(0xFFFFFFFFu, ya, 2);
            xa += __shfl_xor_sync(0xFFFFFFFFu, xa, 4);
            xa += __shfl_xor_sync(0xFFFFFFFFu, xa, 8);
            xa += __shfl_xor_sync(0xFFFFFFFFu, xa, 16);
            float alpha_l = 0.f;
            if (lane < CH && base + lane < e) {
                int idx = base + lane - s;
                float attn;
                if (idx < S_ATT) attn = s_attn[idx];
                else {
                    float x = cc * (xa + b0) * SC;
                    attn = (x > 20.0f) ? x : log1pf(__expf(x));
                }
                alpha_l = attn * inv;
            }
            #pragma unroll
            for (int r = 0; r < CH; r++) {
                int n = base + r;
                if (n >= e) break;
                float al = __shfl_sync(0xFFFFFFFFu, alpha_l, r);
                float4 o;
                o.x = fmaf(al, fmaf(al, fmaf(al, E4.x, C4.x), B4.x), nv[r].x + A4.x);
                o.y = fmaf(al, fmaf(al, fmaf(al, E4.y, C4.y), B4.y), nv[r].y + A4.y);
                o.z = fmaf(al, fmaf(al, fmaf(al, E4.z, C4.z), B4.z), nv[r].z + A4.z);
                o.w = fmaf(al, fmaf(al, fmaf(al, E4.w, C4.w), B4.w), nv[r].w + A4.w);
                __stcs((float4*)(out + (size_t)n * D) + lane, o);
            }
        }
    }
}

// ---------------------------------------------------------------------------
// Launch. Inputs per metadata order:
// 0 node_scalar [N,128] f32, 1 batch [N] i32, 2 spin [G,1] f32,
// 3 Wq [128,128], 4 bq [128], 5 Wk [128,1], 6 Wv [128,1],
// 7 W1 [128,128], 8 b1 [128], 9 W2 [128,128], 10 b2 [128]
// ---------------------------------------------------------------------------
extern "C" void kernel_launch(void* const* d_in, const int* in_sizes, int n_in,
                              void* d_out, int out_size) {
    const float* node  = (const float*)d_in[0];
    const int*   batch = (const int*)d_in[1];
    const float* spin  = (const float*)d_in[2];
    const float* Wq    = (const float*)d_in[3];
    const float* bq    = (const float*)d_in[4];
    const float* Wk    = (const float*)d_in[5];
    const float* Wv    = (const float*)d_in[6];
    const float* W1    = (const float*)d_in[7];
    const float* b1    = (const float*)d_in[8];
    const float* W2    = (const float*)d_in[9];
    const float* b2    = (const float*)d_in[10];
    float* out = (float*)d_out;

    int n_nodes  = in_sizes[0] / D;
    int n_graphs = in_sizes[2];
    if (n_graphs > MAX_GRAPHS) n_graphs = MAX_GRAPHS;

    int sblocks = (n_nodes + 255) / 256;
    if (sblocks < NSLICE) sblocks = NSLICE;
    setup1<<<sblocks, 256>>>(Wq, bq, Wk, Wv, W1, batch, n_nodes, n_graphs);
    setup_fold<<<1, 1024>>>(b1, W2, b2, Wv);
    graph_kernel<<<n_graphs, TPB>>>(node, spin, out);
}

// round 9
// speedup vs baseline: 1.4004x; 1.0514x over previous
#include <cuda_runtime.h>
#include <math.h>

#define D 128
#define MAX_GRAPHS 4096
#define NSLICE 16
#define TPB 128
#define WPB 4              // warps per block
#define CH 8               // nodes per warp per iteration (MLP=8)
#define S_ATT 2048         // smem attn cache (nodes per graph); fallback beyond

// Precomputed small vectors / scratch (no allocation)
__device__ float g_w[D];                          // Wq^T @ Wk
__device__ float g_b0;                            // bq . Wk
__device__ float g_A[D], g_Bp[D], g_C[D], g_E[D]; // fully-collapsed epilogue poly
__device__ float g_pw[NSLICE][D];                 // Wq^T Wk partials
__device__ float g_pu[NSLICE][D];                 // W1 @ Wv partials
__device__ int   g_gs[MAX_GRAPHS + 1];            // graph -> first node index

// ---------------------------------------------------------------------------
// Setup K1: boundary scan + weight partials + b0.   (unchanged from R8)
// ---------------------------------------------------------------------------
__global__ void setup1(const float* __restrict__ Wq,
                       const float* __restrict__ bq,
                       const float* __restrict__ Wk,
                       const float* __restrict__ Wv,
                       const float* __restrict__ W1,
                       const int* __restrict__ batch,
                       int n_nodes, int n_graphs) {
    __shared__ float wk_s[D], wv_s[D];
    __shared__ float red[D];

    int b = blockIdx.x;
    int t = threadIdx.x;

    for (int i = b * blockDim.x + t; i < n_nodes; i += gridDim.x * blockDim.x) {
        int cur = batch[i];
        if (i == 0)
            for (int g = 0; g <= cur; g++) g_gs[g] = 0;
        int nxt = (i + 1 < n_nodes) ? batch[i + 1] : n_graphs;
        for (int g = cur + 1; g <= nxt; g++) g_gs[g] = i + 1;
    }

    if (b >= NSLICE) return;

    int j = t & (D - 1);
    int h = t >> 7;

    if (t < D) { wk_s[t] = Wk[t]; wv_s[t] = Wv[t]; }
    __syncthreads();

    {
        float acc = 0.f;
        #pragma unroll
        for (int m = 0; m < 4; m++) {
            int i = b * 8 + h * 4 + m;
            acc += Wq[i * D + j] * wk_s[i];
        }
        if (h == 1) red[j] = acc;
        __syncthreads();
        if (h == 0) g_pw[b][j] = acc + red[j];
        __syncthreads();
    }
    {
        int k0 = b * 8 + h * 4;
        float4 w4 = *(const float4*)(W1 + (size_t)j * D + k0);
        float acc = w4.x * wv_s[k0] + w4.y * wv_s[k0 + 1]
                  + w4.z * wv_s[k0 + 2] + w4.w * wv_s[k0 + 3];
        if (h == 1) red[j] = acc;
        __syncthreads();
        if (h == 0) g_pu[b][j] = acc + red[j];
    }
    if (b == 0 && t < 32) {
        float acc = 0.f;
        for (int i = t; i < D; i += 32) acc += bq[i] * wk_s[i];
        #pragma unroll
        for (int o = 16; o > 0; o >>= 1) acc += __shfl_xor_sync(0xFFFFFFFFu, acc, o);
        if (t == 0) g_b0 = acc;
    }
}

// ---------------------------------------------------------------------------
// Setup K2: reduce partials, inner silu Taylor, fold W2, outer silu Taylor.
// out = node + A + alpha*B' + alpha^2*C + alpha^3*E   (unchanged from R8)
// ---------------------------------------------------------------------------
__global__ void setup_fold(const float* __restrict__ b1,
                           const float* __restrict__ W2,
                           const float* __restrict__ b2,
                           const float* __restrict__ Wv) {
    __shared__ float c0[D], c1[D], c2[D], c3[D];
    __shared__ float red[8][D];

    int t = threadIdx.x;
    int c = t >> 7;
    int j = t & (D - 1);

    if (c == 0) {
        float s = 0.f;
        #pragma unroll
        for (int p = 0; p < NSLICE; p++) s += g_pw[p][j];
        g_w[j] = s;
    } else if (c == 1) {
        float u = 0.f;
        #pragma unroll
        for (int p = 0; p < NSLICE; p++) u += g_pu[p][j];

        float x  = b1[j];
        float sg = 1.0f / (1.0f + __expf(-x));
        float spd = sg * (1.0f - sg);
        float f0 = x * sg;
        float f1 = sg + x * spd;
        float f2 = spd * (2.0f + x * (1.0f - 2.0f * sg));
        float om2 = 1.0f - 2.0f * sg;
        float f3 = 3.0f * spd * om2 + x * (spd * om2 * om2 - 2.0f * spd * spd);
        c0[j] = f0;
        c1[j] = u * f1;
        c2[j] = u * u * f2 * 0.5f;
        c3[j] = u * u * u * f3 * (1.0f / 6.0f);
    }
    __syncthreads();

    float ap = 0.f, ar = 0.f, at = 0.f, as = 0.f;
    #pragma unroll
    for (int mm = 0; mm < 4; mm++) {
        int k = c * 16 + mm * 4;
        float4 w4 = *(const float4*)(W2 + (size_t)j * D + k);
        ap += w4.x * c0[k] + w4.y * c0[k+1] + w4.z * c0[k+2] + w4.w * c0[k+3];
        ar += w4.x * c1[k] + w4.y * c1[k+1] + w4.z * c1[k+2] + w4.w * c1[k+3];
        at += w4.x * c2[k] + w4.y * c2[k+1] + w4.z * c2[k+2] + w4.w * c2[k+3];
        as += w4.x * c3[k] + w4.y * c3[k+1] + w4.z * c3[k+2] + w4.w * c3[k+3];
    }
    float p_v = 0.f, r_v = 0.f, t_v = 0.f, s_v = 0.f;
    red[c][j] = ap; __syncthreads();
    if (c == 0) { p_v = b2[j];
        #pragma unroll
        for (int p = 0; p < 8; p++) p_v += red[p][j]; }
    __syncthreads();
    red[c][j] = ar; __syncthreads();
    if (c == 0) {
        #pragma unroll
        for (int p = 0; p < 8; p++) r_v += red[p][j]; }
    __syncthreads();
    red[c][j] = at; __syncthreads();
    if (c == 0) {
        #pragma unroll
        for (int p = 0; p < 8; p++) t_v += red[p][j]; }
    __syncthreads();
    red[c][j] = as; __syncthreads();
    if (c == 0) {
        #pragma unroll
        for (int p = 0; p < 8; p++) s_v += red[p][j];

        float x  = p_v;
        float sg = 1.0f / (1.0f + __expf(-x));
        float spd = sg * (1.0f - sg);
        float d0 = x * sg;
        float d1 = sg + x * spd;
        float d2 = spd * (2.0f + x * (1.0f - 2.0f * sg));
        float om2 = 1.0f - 2.0f * sg;
        float d3 = 3.0f * spd * om2 + x * (spd * om2 * om2 - 2.0f * spd * spd);

        g_A[j]  = d0;
        g_Bp[j] = Wv[j] + d1 * r_v;
        g_C[j]  = 0.5f * d2 * r_v * r_v + d1 * t_v;
        g_E[j]  = (1.0f / 6.0f) * d3 * r_v * r_v * r_v + d2 * r_v * t_v + d1 * s_v;
    }
}

// ---------------------------------------------------------------------------
// 9-shfl merge reduce for 8 accumulators: lane l (0..7) ends with node l's dot.
// ---------------------------------------------------------------------------
__device__ __forceinline__ float merge_reduce8(const float a[8], int lane) {
    bool b1 = lane & 1, b2 = lane & 2, b4 = lane & 4;
    float v01 = (b1 ? a[1] : a[0]) + __shfl_xor_sync(0xFFFFFFFFu, b1 ? a[0] : a[1], 1);
    float v23 = (b1 ? a[3] : a[2]) + __shfl_xor_sync(0xFFFFFFFFu, b1 ? a[2] : a[3], 1);
    float v45 = (b1 ? a[5] : a[4]) + __shfl_xor_sync(0xFFFFFFFFu, b1 ? a[4] : a[5], 1);
    float v67 = (b1 ? a[7] : a[6]) + __shfl_xor_sync(0xFFFFFFFFu, b1 ? a[6] : a[7], 1);
    float vA  = (b2 ? v23 : v01) + __shfl_xor_sync(0xFFFFFFFFu, b2 ? v01 : v23, 2);
    float vB  = (b2 ? v67 : v45) + __shfl_xor_sync(0xFFFFFFFFu, b2 ? v45 : v67, 2);
    float vC  = (b4 ? vB : vA)  + __shfl_xor_sync(0xFFFFFFFFu, b4 ? vA : vB, 4);
    vC += __shfl_xor_sync(0xFFFFFFFFu, vC, 8);
    vC += __shfl_xor_sync(0xFFFFFFFFu, vC, 16);
    return vC;     // lane l in [0,8): full dot of node l (replicated mod 8)
}

// ---------------------------------------------------------------------------
// Main kernel: ONE BLOCK PER GRAPH, TPB=128, CH=8.
// Phase A: L1-cached loads, dot -> softplus, attn in smem, block-local sum.
// Phase B: reload rows (L1/L2-hot), pure-FMA cubic epilogue, streaming store.
// ---------------------------------------------------------------------------
__global__ void __launch_bounds__(TPB)
graph_kernel(const float* __restrict__ node,
             const float* __restrict__ spin,
             float* __restrict__ out) {
    __shared__ float s_attn[S_ATT];
    __shared__ float s_wsum[WPB];
    __shared__ float s_total;

    int g    = blockIdx.x;
    int tid  = threadIdx.x;
    int wid  = tid >> 5;
    int lane = tid & 31;

    int s = g_gs[g];
    int e = g_gs[g + 1];
    if (e <= s) return;

    float4 w4 = ((const float4*)g_w)[lane];
    float  b0 = g_b0;
    float  sp = spin[g];
    float  cc = sp / fmaxf(sp, 1.0f);
    const float SC = 0.08838834764831845f;   // 1/sqrt(128)

    // ---------------- Phase A ----------------
    float wacc = 0.f;
    for (int base = s + wid * CH; base < e; base += WPB * CH) {
        float4 v[CH];
        #pragma unroll
        for (int r = 0; r < CH; r++)
            v[r] = (base + r < e)
                ? ((const float4*)(node + (size_t)(base + r) * D))[lane]   // L1-enabled
                : make_float4(0.f, 0.f, 0.f, 0.f);
        float a[CH];
        #pragma unroll
        for (int r = 0; r < CH; r++)
            a[r] = v[r].x*w4.x + v[r].y*w4.y + v[r].z*w4.z + v[r].w*w4.w;
        float dot = merge_reduce8(a, lane);
        if (lane < CH && base + lane < e) {
            float x = cc * (dot + b0) * SC;
            float attn = (x > 20.0f) ? x : log1pf(__expf(x));
            wacc += attn;
            int idx = base + lane - s;
            if (idx < S_ATT) s_attn[idx] = attn;
        }
    }
    #pragma unroll
    for (int o = 16; o > 0; o >>= 1) wacc += __shfl_xor_sync(0xFFFFFFFFu, wacc, o);
    if (lane == 0) s_wsum[wid] = wacc;
    __syncthreads();
    if (tid == 0) {
        float ts = 0.f;
        #pragma unroll
        for (int w = 0; w < WPB; w++) ts += s_wsum[w];
        s_total = ts;
    }
    __syncthreads();
    float inv = sp / s_total;

    // ---------------- Phase B: pure-FMA cubic epilogue ----------------
    float4 A4 = ((const float4*)g_A)[lane];
    float4 B4 = ((const float4*)g_Bp)[lane];
    float4 C4 = ((const float4*)g_C)[lane];
    float4 E4 = ((const float4*)g_E)[lane];

    for (int base = s + wid * CH; base < e; base += WPB * CH) {
        float4 nv[CH];
        #pragma unroll
        for (int r = 0; r < CH; r++)
            nv[r] = (base + r < e)
                ? ((const float4*)(node + (size_t)(base + r) * D))[lane]
                : make_float4(0.f, 0.f, 0.f, 0.f);

        if (base - s + CH <= S_ATT) {
            // fast path: alpha via smem broadcast — no reduce, no silu
            #pragma unroll
            for (int r = 0; r < CH; r++) {
                int n = base + r;
                if (n >= e) break;
                float al = s_attn[n - s] * inv;      // LDS broadcast
                float4 o;
                o.x = fmaf(al, fmaf(al, fmaf(al, E4.x, C4.x), B4.x), nv[r].x + A4.x);
                o.y = fmaf(al, fmaf(al, fmaf(al, E4.y, C4.y), B4.y), nv[r].y + A4.y);
                o.z = fmaf(al, fmaf(al, fmaf(al, E4.z, C4.z), B4.z), nv[r].z + A4.z);
                o.w = fmaf(al, fmaf(al, fmaf(al, E4.w, C4.w), B4.w), nv[r].w + A4.w);
                __stcs((float4*)(out + (size_t)n * D) + lane, o);
            }
        } else {
            // fallback (graphs > S_ATT nodes): recompute attn from reloaded rows
            float a[CH];
            #pragma unroll
            for (int r = 0; r < CH; r++)
                a[r] = nv[r].x*w4.x + nv[r].y*w4.y + nv[r].z*w4.z + nv[r].w*w4.w;
            float dot = merge_reduce8(a, lane);
            float alpha_l = 0.f;
            if (lane < CH && base + lane < e) {
                int idx = base + lane - s;
                float attn;
                if (idx < S_ATT) attn = s_attn[idx];
                else {
                    float x = cc * (dot + b0) * SC;
                    attn = (x > 20.0f) ? x : log1pf(__expf(x));
                }
                alpha_l = attn * inv;
            }
            #pragma unroll
            for (int r = 0; r < CH; r++) {
                int n = base + r;
                if (n >= e) break;
                float al = __shfl_sync(0xFFFFFFFFu, alpha_l, r);
                float4 o;
                o.x = fmaf(al, fmaf(al, fmaf(al, E4.x, C4.x), B4.x), nv[r].x + A4.x);
                o.y = fmaf(al, fmaf(al, fmaf(al, E4.y, C4.y), B4.y), nv[r].y + A4.y);
                o.z = fmaf(al, fmaf(al, fmaf(al, E4.z, C4.z), B4.z), nv[r].z + A4.z);
                o.w = fmaf(al, fmaf(al, fmaf(al, E4.w, C4.w), B4.w), nv[r].w + A4.w);
                __stcs((float4*)(out + (size_t)n * D) + lane, o);
            }
        }
    }
}

// ---------------------------------------------------------------------------
// Launch. Inputs per metadata order:
// 0 node_scalar [N,128] f32, 1 batch [N] i32, 2 spin [G,1] f32,
// 3 Wq [128,128], 4 bq [128], 5 Wk [128,1], 6 Wv [128,1],
// 7 W1 [128,128], 8 b1 [128], 9 W2 [128,128], 10 b2 [128]
// ---------------------------------------------------------------------------
extern "C" void kernel_launch(void* const* d_in, const int* in_sizes, int n_in,
                              void* d_out, int out_size) {
    const float* node  = (const float*)d_in[0];
    const int*   batch = (const int*)d_in[1];
    const float* spin  = (const float*)d_in[2];
    const float* Wq    = (const float*)d_in[3];
    const float* bq    = (const float*)d_in[4];
    const float* Wk    = (const float*)d_in[5];
    const float* Wv    = (const float*)d_in[6];
    const float* W1    = (const float*)d_in[7];
    const float* b1    = (const float*)d_in[8];
    const float* W2    = (const float*)d_in[9];
    const float* b2    = (const float*)d_in[10];
    float* out = (float*)d_out;

    int n_nodes  = in_sizes[0] / D;
    int n_graphs = in_sizes[2];
    if (n_graphs > MAX_GRAPHS) n_graphs = MAX_GRAPHS;

    int sblocks = (n_nodes + 255) / 256;
    if (sblocks < NSLICE) sblocks = NSLICE;
    setup1<<<sblocks, 256>>>(Wq, bq, Wk, Wv, W1, batch, n_nodes, n_graphs);
    setup_fold<<<1, 1024>>>(b1, W2, b2, Wv);
    graph_kernel<<<n_graphs, TPB>>>(node, spin, out);
}